// round 1
// baseline (speedup 1.0000x reference)
#include <cuda_runtime.h>
#include <math.h>

#define SS 1024
#define CC 4096
#define KK 4

// ---------------- scratch (no allocations allowed) ----------------
__device__ float g_w[8 * SS];      // exp(log_Pi[c] - m_c) for the 8 split rows
__device__ float g_m[8];           // row maxes
__device__ float g_sums[8 * SS];   // raw dots  sum_j w[c][j] * recip[s][j]
__device__ float g_logcnt[SS];
__device__ float g_logE[SS];
__device__ float g_consts[8];      // 0..3: pS,pD,pT,pL ; 4..6: lpS,lpD,lpT ; 7: leaf flag
__device__ int   g_c[8];           // c1[0..3], c2[0..3]
__device__ int   g_root;

__device__ __forceinline__ float softplusf(float x) {
    if (x > 20.0f)  return x;
    if (x < -20.0f) return expf(x);
    return log1pf(expf(x));
}

// logaddexp, stable
__device__ __forceinline__ float laef(float a, float b) {
    float mx = fmaxf(a, b);
    float mn = fminf(a, b);
    return mx + log1pf(expf(mn - mx));
}

// ---------------- kernel 1: scalars + split-row max/weights ----------------
__global__ void k_prep(const float* __restrict__ log_delta,
                       const float* __restrict__ log_tau,
                       const float* __restrict__ log_lambda,
                       const float* __restrict__ logPi,
                       const int*   __restrict__ splits_c1,
                       const int*   __restrict__ splits_c2,
                       const void*  __restrict__ is_leaf,
                       const int*   __restrict__ rootp)
{
    __shared__ int sc[8];
    int tid = threadIdx.x;
    if (tid == 0) {
        int root = rootp[0];
        g_root = root;
        float delta = softplusf(log_delta[0]);
        float tau   = softplusf(log_tau[0]);
        float lam   = softplusf(log_lambda[0]);
        float rs = 1.0f + delta + tau + lam;
        float pS = 1.0f / rs, pD = delta / rs, pT = tau / rs, pL = lam / rs;
        g_consts[0] = pS; g_consts[1] = pD; g_consts[2] = pT; g_consts[3] = pL;
        g_consts[4] = logf(pS); g_consts[5] = logf(pD); g_consts[6] = logf(pT);
        // leaf flag, robust to serialization dtype:
        //  - bool/uint8 layout: byte[root] in {0,1}
        //  - int32 layout (0/1): low byte of word[root] equals the value
        //  - float32 layout: word[root] == bits of 1.0f
        const unsigned char* lb = (const unsigned char*)is_leaf;
        const unsigned int*  lw = (const unsigned int*)is_leaf;
        bool leaf = (lb[root] != 0) || (lw[root] == 0x3F800000u);
        g_consts[7] = leaf ? 1.0f : 0.0f;
        #pragma unroll
        for (int k = 0; k < KK; k++) {
            sc[k]     = splits_c1[root * KK + k];
            sc[4 + k] = splits_c2[root * KK + k];
        }
        #pragma unroll
        for (int k = 0; k < 8; k++) g_c[k] = sc[k];
    }
    __syncthreads();

    // 8 warps: warp w handles slot w (one of the 8 split rows)
    int w = tid >> 5, lane = tid & 31;
    int c = sc[w];
    const float* row = logPi + (size_t)c * SS;
    float mx = -INFINITY;
    #pragma unroll 4
    for (int j = lane; j < SS; j += 32) mx = fmaxf(mx, row[j]);
    #pragma unroll
    for (int o = 16; o > 0; o >>= 1) mx = fmaxf(mx, __shfl_xor_sync(0xffffffffu, mx, o));
    mx = __shfl_sync(0xffffffffu, mx, 0);
    if (lane == 0) g_m[w] = mx;
    #pragma unroll 4
    for (int j = lane; j < SS; j += 32) g_w[w * SS + j] = expf(row[j] - mx);
}

// ---------------- kernel 2: one streaming pass over Recipients_mat ----------------
// Block s computes: cnt[s], Ebar[s] -> E_new/logE[s], and 8 weighted dots sums[k][s].
__global__ void __launch_bounds__(256) k_rows(const float* __restrict__ recip,
                                              const float* __restrict__ E,
                                              const int*   __restrict__ sC1,
                                              const int*   __restrict__ sC2)
{
    int s   = blockIdx.x;
    int tid = threadIdx.x;   // 256 threads, one float4 each over the 1024-wide row

    const float4 rv = ((const float4*)(recip + (size_t)s * SS))[tid];
    const float4 ev = ((const float4*)E)[tid];

    float acc[10];
    acc[0] = rv.x + rv.y + rv.z + rv.w;
    acc[1] = rv.x * ev.x + rv.y * ev.y + rv.z * ev.z + rv.w * ev.w;
    #pragma unroll
    for (int k = 0; k < 8; k++) {
        const float4 wv = ((const float4*)(g_w + k * SS))[tid];
        acc[2 + k] = rv.x * wv.x + rv.y * wv.y + rv.z * wv.z + rv.w * wv.w;
    }

    // warp reduce all 10, then cross-warp via smem
    #pragma unroll
    for (int q = 0; q < 10; q++)
        #pragma unroll
        for (int o = 16; o > 0; o >>= 1)
            acc[q] += __shfl_xor_sync(0xffffffffu, acc[q], o);

    __shared__ float sm[8][10];
    int w = tid >> 5, lane = tid & 31;
    if (lane == 0)
        #pragma unroll
        for (int q = 0; q < 10; q++) sm[w][q] = acc[q];
    __syncthreads();

    if (tid == 0) {
        float tot[10];
        #pragma unroll
        for (int q = 0; q < 10; q++) {
            float t = 0.0f;
            #pragma unroll
            for (int w2 = 0; w2 < 8; w2++) t += sm[w2][q];
            tot[q] = t;
        }
        float cnt = fmaxf(tot[0], 1.0f);
        g_logcnt[s] = logf(cnt);
        float Ebar = tot[1] / cnt;
        float pS = g_consts[0], pD = g_consts[1], pT = g_consts[2], pL = g_consts[3];
        float Es = E[s];
        float Enew = pL + pD * Es * Es + pT * Es * Ebar + pS * E[sC1[s]] * E[sC2[s]];
        g_logE[s] = logf(Enew);
        #pragma unroll
        for (int k = 0; k < 8; k++) g_sums[k * SS + s] = tot[2 + k];
    }
}

// ---------------- kernel 3: root-row epilogue + global LSE ----------------
__global__ void __launch_bounds__(1024) k_final(const float* __restrict__ logPi,
                                                const float* __restrict__ log_q,
                                                const int*   __restrict__ sC1,
                                                const int*   __restrict__ sC2,
                                                float*       __restrict__ out)
{
    int s    = threadIdx.x;          // one thread per s in [0, S)
    int root = g_root;
    bool leaf = g_consts[7] > 0.5f;

    float m_loc, s_loc;
    if (leaf) {
        m_loc = logPi[(size_t)root * SS + s];
        s_loc = 1.0f;
    } else {
        float lpS = g_consts[4], lpD = g_consts[5], lpT = g_consts[6];
        int i1 = sC1[s], i2 = sC2[s];
        float lct = g_logcnt[s];

        float speck[KK], dupk[KK], trk[KK];
        float specm = -INFINITY, dupm = -INFINITY, trm = -INFINITY;
        #pragma unroll
        for (int k = 0; k < KK; k++) {
            int c1 = g_c[k], c2 = g_c[4 + k];
            const float* rA = logPi + (size_t)c1 * SS;
            const float* rB = logPi + (size_t)c2 * SS;
            float a  = rA[s],  b  = rB[s];
            float af = rA[i1], ag = rA[i2];
            float bf = rB[i1], bg = rB[i2];
            float lq = log_q[root * KK + k];

            speck[k] = lq + laef(af + bg, ag + bf);
            dupk[k]  = lq + a + b;
            float tbA = logf(fmaxf(g_sums[k * SS + s],        1e-30f)) - lct + g_m[k];
            float tbB = logf(fmaxf(g_sums[(4 + k) * SS + s],  1e-30f)) - lct + g_m[4 + k];
            trk[k] = lq + laef(a + tbB, b + tbA);

            specm = fmaxf(specm, speck[k]);
            dupm  = fmaxf(dupm,  dupk[k]);
            trm   = fmaxf(trm,   trk[k]);
        }
        float se = 0.0f, de = 0.0f, te = 0.0f;
        #pragma unroll
        for (int k = 0; k < KK; k++) {
            se += expf(speck[k] - specm);
            de += expf(dupk[k]  - dupm);
            te += expf(trk[k]   - trm);
        }
        float spec  = lpS + specm + logf(se);
        float dup   = lpD + dupm  + logf(de);
        float trans = lpT + trm   + logf(te);
        float sl    = lpS + laef(logPi[(size_t)root * SS + i1] + g_logE[i2],
                                 logPi[(size_t)root * SS + i2] + g_logE[i1]);

        float mx = fmaxf(fmaxf(spec, dup), fmaxf(trans, sl));
        m_loc = mx;
        s_loc = expf(spec - mx) + expf(dup - mx) + expf(trans - mx) + expf(sl - mx);
    }

    // block-wide online LSE reduction over 1024 (m, sum) pairs
    __shared__ float shm[SS];
    __shared__ float shs[SS];
    shm[s] = m_loc; shs[s] = s_loc;
    __syncthreads();
    for (int stride = 512; stride > 0; stride >>= 1) {
        if (s < stride) {
            float m1 = shm[s], s1 = shs[s];
            float m2 = shm[s + stride], s2 = shs[s + stride];
            float M = fmaxf(m1, m2);
            shm[s] = M;
            shs[s] = s1 * expf(m1 - M) + s2 * expf(m2 - M);
        }
        __syncthreads();
    }
    if (s == 0) out[0] = shm[0] + logf(shs[0]);
}

// ---------------- launch ----------------
extern "C" void kernel_launch(void* const* d_in, const int* in_sizes, int n_in,
                              void* d_out, int out_size)
{
    const float* log_delta  = (const float*)d_in[0];
    const float* log_tau    = (const float*)d_in[1];
    const float* log_lambda = (const float*)d_in[2];
    const float* E          = (const float*)d_in[3];
    const float* log_Pi     = (const float*)d_in[4];
    const int*   s_C1       = (const int*)  d_in[5];
    const int*   s_C2       = (const int*)  d_in[6];
    const float* recip      = (const float*)d_in[7];
    const int*   splits_c1  = (const int*)  d_in[8];
    const int*   splits_c2  = (const int*)  d_in[9];
    const float* log_q      = (const float*)d_in[10];
    const void*  is_leaf    = (const void*) d_in[11];
    const int*   root_id    = (const int*)  d_in[12];
    float* out = (float*)d_out;

    k_prep<<<1, 256>>>(log_delta, log_tau, log_lambda, log_Pi,
                       splits_c1, splits_c2, is_leaf, root_id);
    k_rows<<<SS, 256>>>(recip, E, s_C1, s_C2);
    k_final<<<1, 1024>>>(log_Pi, log_q, s_C1, s_C2, out);
}

// round 2
// speedup vs baseline: 1.0122x; 1.0122x over previous
#include <cuda_runtime.h>
#include <math.h>

#define SS 1024
#define CC 4096
#define KK 4

// ---------------- scratch (no allocations allowed) ----------------
__device__ float g_w[8 * SS];      // exp(log_Pi[c]) for the 8 split rows (no max shift needed)
__device__ float g_sums[8 * SS];   // raw dots  sum_j w[c][j] * recip[s][j]
__device__ float g_logcnt[SS];
__device__ float g_logE[SS];
__device__ float g_consts[8];      // 0..3: pS,pD,pT,pL ; 4..6: lpS,lpD,lpT ; 7: leaf flag
__device__ int   g_c[8];           // c1[0..3], c2[0..3]
__device__ int   g_root;

__device__ __forceinline__ float softplusf(float x) {
    if (x > 20.0f)  return x;
    if (x < -20.0f) return expf(x);
    return log1pf(expf(x));
}

__device__ __forceinline__ float laef(float a, float b) {
    float mx = fmaxf(a, b);
    float mn = fminf(a, b);
    return mx + log1pf(expf(mn - mx));
}

// ---------------- kernel 1: scalars + split-row exp weights ----------------
// grid = 9 blocks x 256 threads.
// Blocks 0..7: one split row each, single pass: load float4 -> exp -> store.
// Block 8: thread 0 computes scalar constants (runs concurrently).
__global__ void __launch_bounds__(256) k_prep(const float* __restrict__ log_delta,
                                              const float* __restrict__ log_tau,
                                              const float* __restrict__ log_lambda,
                                              const float* __restrict__ logPi,
                                              const int*   __restrict__ splits_c1,
                                              const int*   __restrict__ splits_c2,
                                              const void*  __restrict__ is_leaf,
                                              const int*   __restrict__ rootp)
{
    int b   = blockIdx.x;
    int tid = threadIdx.x;

    if (b == 8) {
        if (tid == 0) {
            int root = rootp[0];
            g_root = root;
            float delta = softplusf(log_delta[0]);
            float tau   = softplusf(log_tau[0]);
            float lam   = softplusf(log_lambda[0]);
            float rs = 1.0f + delta + tau + lam;
            float pS = 1.0f / rs, pD = delta / rs, pT = tau / rs, pL = lam / rs;
            g_consts[0] = pS; g_consts[1] = pD; g_consts[2] = pT; g_consts[3] = pL;
            g_consts[4] = logf(pS); g_consts[5] = logf(pD); g_consts[6] = logf(pT);
            // leaf flag, robust to serialization dtype (bool/uint8, int32, or float32)
            const unsigned char* lb = (const unsigned char*)is_leaf;
            const unsigned int*  lw = (const unsigned int*)is_leaf;
            bool leaf = (lb[root] != 0) || (lw[root] == 0x3F800000u);
            g_consts[7] = leaf ? 1.0f : 0.0f;
        }
        return;
    }

    // every thread loads root (same address -> broadcast) and its split index
    int root = rootp[0];
    int c = (b < 4) ? splits_c1[root * KK + b] : splits_c2[root * KK + (b - 4)];
    if (tid == 0) g_c[b] = c;

    const float4 v = ((const float4*)(logPi + (size_t)c * SS))[tid];
    float4 w;
    w.x = expf(v.x); w.y = expf(v.y); w.z = expf(v.z); w.w = expf(v.w);
    ((float4*)(g_w + b * SS))[tid] = w;
}

// ---------------- kernel 2: one streaming pass over Recipients_mat ----------------
// Block s computes: cnt[s], Ebar[s] -> E_new/logE[s], and 8 weighted dots sums[k][s].
__global__ void __launch_bounds__(256) k_rows(const float* __restrict__ recip,
                                              const float* __restrict__ E,
                                              const int*   __restrict__ sC1,
                                              const int*   __restrict__ sC2)
{
    int s   = blockIdx.x;
    int tid = threadIdx.x;   // 256 threads, one float4 each over the 1024-wide row

    const float4 rv = ((const float4*)(recip + (size_t)s * SS))[tid];
    const float4 ev = ((const float4*)E)[tid];

    float acc[10];
    acc[0] = rv.x + rv.y + rv.z + rv.w;
    acc[1] = rv.x * ev.x + rv.y * ev.y + rv.z * ev.z + rv.w * ev.w;
    #pragma unroll
    for (int k = 0; k < 8; k++) {
        const float4 wv = ((const float4*)(g_w + k * SS))[tid];
        acc[2 + k] = rv.x * wv.x + rv.y * wv.y + rv.z * wv.z + rv.w * wv.w;
    }

    #pragma unroll
    for (int q = 0; q < 10; q++)
        #pragma unroll
        for (int o = 16; o > 0; o >>= 1)
            acc[q] += __shfl_xor_sync(0xffffffffu, acc[q], o);

    __shared__ float sm[8][10];
    int w = tid >> 5, lane = tid & 31;
    if (lane == 0)
        #pragma unroll
        for (int q = 0; q < 10; q++) sm[w][q] = acc[q];
    __syncthreads();

    if (tid == 0) {
        float tot[10];
        #pragma unroll
        for (int q = 0; q < 10; q++) {
            float t = 0.0f;
            #pragma unroll
            for (int w2 = 0; w2 < 8; w2++) t += sm[w2][q];
            tot[q] = t;
        }
        float cnt = fmaxf(tot[0], 1.0f);
        g_logcnt[s] = logf(cnt);
        float Ebar = tot[1] / cnt;
        float pS = g_consts[0], pD = g_consts[1], pT = g_consts[2], pL = g_consts[3];
        float Es = E[s];
        float Enew = pL + pD * Es * Es + pT * Es * Ebar + pS * E[sC1[s]] * E[sC2[s]];
        g_logE[s] = logf(Enew);
        #pragma unroll
        for (int k = 0; k < 8; k++) g_sums[k * SS + s] = tot[2 + k];
    }
}

// ---------------- kernel 3: root-row epilogue + global LSE ----------------
__global__ void __launch_bounds__(1024) k_final(const float* __restrict__ logPi,
                                                const float* __restrict__ log_q,
                                                const int*   __restrict__ sC1,
                                                const int*   __restrict__ sC2,
                                                float*       __restrict__ out)
{
    int s    = threadIdx.x;          // one thread per s in [0, S)
    int root = g_root;
    bool leaf = g_consts[7] > 0.5f;

    float m_loc, s_loc;
    if (leaf) {
        m_loc = logPi[(size_t)root * SS + s];
        s_loc = 1.0f;
    } else {
        float lpS = g_consts[4], lpD = g_consts[5], lpT = g_consts[6];
        int i1 = sC1[s], i2 = sC2[s];
        float lct = g_logcnt[s];

        float speck[KK], dupk[KK], trk[KK];
        float specm = -INFINITY, dupm = -INFINITY, trm = -INFINITY;
        #pragma unroll
        for (int k = 0; k < KK; k++) {
            int c1 = g_c[k], c2 = g_c[4 + k];
            const float* rA = logPi + (size_t)c1 * SS;
            const float* rB = logPi + (size_t)c2 * SS;
            float a  = rA[s],  b  = rB[s];
            float af = rA[i1], ag = rA[i2];
            float bf = rB[i1], bg = rB[i2];
            float lq = log_q[root * KK + k];

            speck[k] = lq + laef(af + bg, ag + bf);
            dupk[k]  = lq + a + b;
            // logTbar = log(max(raw_sum,1e-30)) - log(cnt)   (max-shift m == 0, exact identity)
            float tbA = logf(fmaxf(g_sums[k * SS + s],       1e-30f)) - lct;
            float tbB = logf(fmaxf(g_sums[(4 + k) * SS + s], 1e-30f)) - lct;
            trk[k] = lq + laef(a + tbB, b + tbA);

            specm = fmaxf(specm, speck[k]);
            dupm  = fmaxf(dupm,  dupk[k]);
            trm   = fmaxf(trm,   trk[k]);
        }
        float se = 0.0f, de = 0.0f, te = 0.0f;
        #pragma unroll
        for (int k = 0; k < KK; k++) {
            se += expf(speck[k] - specm);
            de += expf(dupk[k]  - dupm);
            te += expf(trk[k]   - trm);
        }
        float spec  = lpS + specm + logf(se);
        float dup   = lpD + dupm  + logf(de);
        float trans = lpT + trm   + logf(te);
        float sl    = lpS + laef(logPi[(size_t)root * SS + i1] + g_logE[i2],
                                 logPi[(size_t)root * SS + i2] + g_logE[i1]);

        float mx = fmaxf(fmaxf(spec, dup), fmaxf(trans, sl));
        m_loc = mx;
        s_loc = expf(spec - mx) + expf(dup - mx) + expf(trans - mx) + expf(sl - mx);
    }

    // block-wide online LSE reduction over 1024 (m, sum) pairs
    __shared__ float shm[SS];
    __shared__ float shs[SS];
    shm[s] = m_loc; shs[s] = s_loc;
    __syncthreads();
    for (int stride = 512; stride > 0; stride >>= 1) {
        if (s < stride) {
            float m1 = shm[s], s1 = shs[s];
            float m2 = shm[s + stride], s2 = shs[s + stride];
            float M = fmaxf(m1, m2);
            shm[s] = M;
            shs[s] = s1 * expf(m1 - M) + s2 * expf(m2 - M);
        }
        __syncthreads();
    }
    if (s == 0) out[0] = shm[0] + logf(shs[0]);
}

// ---------------- launch ----------------
extern "C" void kernel_launch(void* const* d_in, const int* in_sizes, int n_in,
                              void* d_out, int out_size)
{
    const float* log_delta  = (const float*)d_in[0];
    const float* log_tau    = (const float*)d_in[1];
    const float* log_lambda = (const float*)d_in[2];
    const float* E          = (const float*)d_in[3];
    const float* log_Pi     = (const float*)d_in[4];
    const int*   s_C1       = (const int*)  d_in[5];
    const int*   s_C2       = (const int*)  d_in[6];
    const float* recip      = (const float*)d_in[7];
    const int*   splits_c1  = (const int*)  d_in[8];
    const int*   splits_c2  = (const int*)  d_in[9];
    const float* log_q      = (const float*)d_in[10];
    const void*  is_leaf    = (const void*) d_in[11];
    const int*   root_id    = (const int*)  d_in[12];
    float* out = (float*)d_out;

    k_prep<<<9, 256>>>(log_delta, log_tau, log_lambda, log_Pi,
                       splits_c1, splits_c2, is_leaf, root_id);
    k_rows<<<SS, 256>>>(recip, E, s_C1, s_C2);
    k_final<<<1, 1024>>>(log_Pi, log_q, s_C1, s_C2, out);
}